// round 5
// baseline (speedup 1.0000x reference)
#include <cuda_runtime.h>

#define PN 16800
#define ON 64
#define BN 64
#define FULLMASK 0xffffffffu

// ---------------- scratch ----------------
__device__ unsigned long long g_bp[BN * ON];
__device__ float g_btov[BN * PN];
__device__ unsigned char g_btidx[BN * PN];
__device__ float g_rank[BN * PN];
__device__ float g_acc[3];
__device__ int g_cnt[2];
__device__ int g_np[BN];
__device__ int g_done;

// =================== matching kernel ===================
// grid (21, 64): bx 0-19 best-truth tiles; bx==20 best-prior per truth + resets
__global__ void __launch_bounds__(256) k_match(
    const float4* __restrict__ priors,
    const float* __restrict__ targets)
{
    const int b = blockIdx.y;
    const int bx = blockIdx.x;
    const int tid = threadIdx.x;
    const int lane = tid & 31;
    const int wid = tid >> 5;

    __shared__ float tX1[ON], tX2[ON], tY1[ON], tY2[ON], tA[ON];

    if (tid < ON) {
        const float* t = targets + (size_t)(b * ON + tid) * 15;
        float x1 = t[0], y1 = t[1], x2 = t[2], y2 = t[3];
        tX1[tid] = x1; tY1[tid] = y1; tX2[tid] = x2; tY2[tid] = y2;
        tA[tid] = (x2 - x1) * (y2 - y1);
    }

    if (bx == 20) {
        __shared__ float b_px1[280], b_px2[280], b_py1[280], b_py2[280];
        if (tid < 3) g_acc[tid] = 0.f;
        if (tid >= 3 && tid < 5) g_cnt[tid - 3] = 0;
        if (tid == 5) g_np[b] = 0;

        for (int t = tid; t < 280; t += 256) {
            int g = (t < 80) ? 0 : (t < 160) ? 1 : (t < 200) ? 2 : (t < 240) ? 3 : (t < 260) ? 4 : 5;
            int off = (g == 0) ? 0 : (g == 1) ? 80 : (g == 2) ? 160 : (g == 3) ? 200 : (g == 4) ? 240 : 260;
            int f = (g < 2) ? 80 : (g < 4) ? 40 : 20;
            int base = (g == 0) ? 0 : (g == 1) ? 6400 : (g == 2) ? 12800 :
                       (g == 3) ? 14400 : (g == 4) ? 16000 : 16400;
            int j = t - off;
            float4 q = priors[base + j];
            b_px1[t] = q.x - q.z * 0.5f; b_px2[t] = q.x + q.z * 0.5f;
            float4 qy = priors[base + j * f];
            b_py1[t] = qy.y - qy.w * 0.5f; b_py2[t] = qy.y + qy.w * 0.5f;
        }
        __syncthreads();

        const int GF[6]   = {80, 80, 40, 40, 20, 20};
        const int GBASE[6]= {0, 6400, 12800, 14400, 16000, 16400};
        const int GOFF[6] = {0, 80, 160, 200, 240, 260};

        for (int it = 0; it < 8; it++) {
            const int o = wid * 8 + it;
            const float X1 = tX1[o], X2 = tX2[o], Y1 = tY1[o], Y2 = tY2[o], A = tA[o];
            unsigned long long best = 0ull;
#pragma unroll
            for (int g = 0; g < 6; g++) {
                const int f = GF[g], co = GOFF[g], base = GBASE[g];
                float bwx = -1.f; int bj = lane;
                for (int j = lane; j < f; j += 32) {
                    float v = fmaxf(fminf(X2, b_px2[co + j]) - fmaxf(X1, b_px1[co + j]), 0.f);
                    if (v > bwx) { bwx = v; bj = j; }
                }
                float bwy = -1.f; int bi2 = lane;
                for (int i = lane; i < f; i += 32) {
                    float v = fmaxf(fminf(Y2, b_py2[co + i]) - fmaxf(Y1, b_py1[co + i]), 0.f);
                    if (v > bwy) { bwy = v; bi2 = i; }
                }
#pragma unroll
                for (int s = 16; s; s >>= 1) {
                    float ov = __shfl_xor_sync(FULLMASK, bwx, s);
                    int oj = __shfl_xor_sync(FULLMASK, bj, s);
                    if (ov > bwx || (ov == bwx && oj < bj)) { bwx = ov; bj = oj; }
                    float ov2 = __shfl_xor_sync(FULLMASK, bwy, s);
                    int oi = __shfl_xor_sync(FULLMASK, bi2, s);
                    if (ov2 > bwy || (ov2 == bwy && oi < bi2)) { bwy = ov2; bi2 = oi; }
                }
                float P = bwx * bwy;
                float dx = b_px2[co + bj] - b_px1[co + bj];
                float dy = b_py2[co + bi2] - b_py1[co + bi2];
                float den = (A + dx * dy) - P;
                float iou = __fdiv_rn(P, den);
                unsigned pidx = (unsigned)(base + bi2 * f + bj);
                unsigned long long key =
                    ((unsigned long long)__float_as_uint(iou) << 32) |
                    (unsigned long long)(0xFFFFFFFFu - pidx);
                if (key > best) best = key;
            }
            if (lane == 0) g_bp[b * ON + o] = best;
        }
        return;
    }

    int g, blk;
    if (bx < 7)       { g = 0; blk = bx; }
    else if (bx < 14) { g = 1; blk = bx - 7; }
    else if (bx < 16) { g = 2; blk = bx - 14; }
    else if (bx < 18) { g = 3; blk = bx - 16; }
    else if (bx == 18){ g = 4; blk = 0; }
    else              { g = 5; blk = 0; }
    const int f    = (g < 2) ? 80 : (g < 4) ? 40 : 20;
    const int base = (g == 0) ? 0 : (g == 1) ? 6400 : (g == 2) ? 12800 :
                     (g == 3) ? 14400 : (g == 4) ? 16000 : 16400;
    const int off  = blk * 1024;
    const int n    = min(1024, f * f - off);
    const int i0   = off / f;
    const int nrows = (off + n - 1) / f - i0 + 1;

    __shared__ float s_wx[ON * 80];
    __shared__ float s_wy[ON * 28];
    __shared__ float s_px1[80], s_px2[80], s_dx[80];
    __shared__ float s_py1[28], s_py2[28], s_dy[28];
    __shared__ float cA[ON];
    __shared__ int   cO[ON];
    __shared__ int   s_cnt;

    if (tid >= 64 && tid < 144) {
        int j = tid - 64;
        if (j < f) {
            float4 q = priors[base + j];
            float a = q.x - q.z * 0.5f, c = q.x + q.z * 0.5f;
            s_px1[j] = a; s_px2[j] = c; s_dx[j] = c - a;
        }
    }
    if (tid >= 160 && tid < 192) {
        int r = tid - 160;
        if (r < nrows) {
            float4 q = priors[base + (i0 + r) * f];
            float a = q.y - q.w * 0.5f, c = q.y + q.w * 0.5f;
            s_py1[r] = a; s_py2[r] = c; s_dy[r] = c - a;
        }
    }
    __syncthreads();

    for (int o = wid; o < ON; o += 8) {
        float X1 = tX1[o], X2 = tX2[o];
        for (int j = lane; j < f; j += 32)
            s_wx[o * 80 + j] = fmaxf(fminf(X2, s_px2[j]) - fmaxf(X1, s_px1[j]), 0.f);
        float Y1 = tY1[o], Y2 = tY2[o];
        if (lane < 28)
            s_wy[o * 28 + lane] = (lane < 28 && lane < nrows)
                ? fmaxf(fminf(Y2, s_py2[lane]) - fmaxf(Y1, s_py1[lane]), 0.f)
                : 0.f;
    }
    __syncthreads();

    if (tid < 32) {
        float ylo = s_py1[0], yhi = s_py2[nrows - 1];
        unsigned lml = (1u << tid) - 1u;
        int o1 = tid, o2 = tid + 32;
        bool k1 = (tY1[o1] < yhi) && (tY2[o1] > ylo);
        bool k2 = (tY1[o2] < yhi) && (tY2[o2] > ylo);
        unsigned m1 = __ballot_sync(FULLMASK, k1);
        unsigned m2 = __ballot_sync(FULLMASK, k2);
        int n1 = __popc(m1);
        if (k1) { int d = __popc(m1 & lml); cO[d] = o1; cA[d] = tA[o1]; }
        if (k2) { int d = n1 + __popc(m2 & lml); cO[d] = o2; cA[d] = tA[o2]; }
        if (tid == 0) s_cnt = n1 + __popc(m2);
    }
    __syncthreads();

    int jj4[4], rr4[4], pg[4];
    float pa[4], bi[4], bd[4];
    int bo[4];
#pragma unroll
    for (int k = 0; k < 4; k++) {
        bi[k] = 0.f; bd[k] = 1.f; bo[k] = 0;
        int l = tid + k * 256;
        if (l < n) {
            int gi = off + l;
            int i = gi / f;
            int j = gi - i * f;
            rr4[k] = i - i0; jj4[k] = j;
            pa[k] = s_dx[j] * s_dy[i - i0];
            pg[k] = base + gi;
        } else {
            rr4[k] = 27; jj4[k] = 0; pa[k] = 0.f; pg[k] = 0;
        }
    }

    const int cnt = s_cnt;
    for (int c = 0; c < cnt; c++) {
        const int oid = cO[c];
        const float* wyo = s_wy + oid * 28;
        float wy0 = wyo[rr4[0]], wy1 = wyo[rr4[1]];
        float wy2 = wyo[rr4[2]], wy3 = wyo[rr4[3]];
        if (((wy0 + wy1) + (wy2 + wy3)) == 0.f) continue;   // zero overlap can't win
        const float A = cA[c];
        const float* wxo = s_wx + oid * 80;
        float wy[4] = {wy0, wy1, wy2, wy3};
#pragma unroll
        for (int k = 0; k < 4; k++) {
            float inter = wxo[jj4[k]] * wy[k];
            float den = (A + pa[k]) - inter;
            if (inter * bd[k] > bi[k] * den) { bi[k] = inter; bd[k] = den; bo[k] = oid; }
        }
    }

#pragma unroll
    for (int k = 0; k < 4; k++) {
        int l = tid + k * 256;
        if (l < n) {
            g_btov[(size_t)b * PN + pg[k]] = __fdiv_rn(bi[k], bd[k]);
            g_btidx[(size_t)b * PN + pg[k]] = (unsigned char)bo[k];
        }
    }
}

// =================== loss helpers ===================
__device__ __forceinline__ float sl1(float x) {
    float a = fabsf(x);
    return a < 1.f ? 0.5f * a * a : a - 0.5f;
}
__device__ __forceinline__ float warp_sumf(float v) {
#pragma unroll
    for (int s = 16; s; s >>= 1) v += __shfl_xor_sync(FULLMASK, v, s);
    return v;
}
__device__ __forceinline__ int warp_sumi(int v) {
#pragma unroll
    for (int s = 16; s; s >>= 1) v += __shfl_xor_sync(FULLMASK, v, s);
    return v;
}

// =================== loss A: per-prior work, grid (8, 64) x 256 ===================
#define RNG 2100

__global__ void __launch_bounds__(256) k_lossA(
    const float* __restrict__ loc,
    const float* __restrict__ conf,
    const float* __restrict__ landm,
    const float4* __restrict__ priors,
    const float* __restrict__ targets)
{
    const int b = blockIdx.y;
    const int r0 = blockIdx.x * RNG;
    const int tid = threadIdx.x;
    const int lane = tid & 31;

    __shared__ float s_ov[RNG];
    __shared__ unsigned char s_id[RNG];
    __shared__ float s_t[ON * 4];
    __shared__ float s_lm[ON * 10];
    __shared__ int s_lab[ON];
    __shared__ unsigned long long s_keys[ON];
    __shared__ int s_any;
    __shared__ float r_ll, r_lm, r_ce;
    __shared__ int r_np, r_np1;

    if (tid == 0) { r_ll = 0.f; r_lm = 0.f; r_ce = 0.f; r_np = 0; r_np1 = 0; }

    for (int i = tid; i < RNG; i += 256) {
        s_ov[i] = g_btov[(size_t)b * PN + r0 + i];
        s_id[i] = g_btidx[(size_t)b * PN + r0 + i];
    }
    if (tid < ON) {
        const float* t = targets + (size_t)(b * ON + tid) * 15;
        s_t[tid * 4 + 0] = t[0]; s_t[tid * 4 + 1] = t[1];
        s_t[tid * 4 + 2] = t[2]; s_t[tid * 4 + 3] = t[3];
#pragma unroll
        for (int j = 0; j < 10; j++) s_lm[tid * 10 + j] = t[4 + j];
        s_lab[tid] = (int)t[14];
        s_keys[tid] = g_bp[b * ON + tid];
    }
    __syncthreads();

    if (tid == 0) {
        unsigned js[ON]; int vld[ON]; float oldv[ON];
        int any = 0;
        for (int o = 0; o < ON; o++) {
            unsigned long long key = s_keys[o];
            unsigned j = 0xFFFFFFFFu - (unsigned)(key & 0xFFFFFFFFull);
            js[o] = j;
            vld[o] = (__uint_as_float((unsigned)(key >> 32)) >= 0.2f);
            any |= vld[o];
            oldv[o] = (j >= (unsigned)r0 && j < (unsigned)(r0 + RNG)) ? s_ov[j - r0] : 0.f;
        }
        for (int o = 0; o < ON; o++) {
            unsigned j = js[o];
            if (j >= (unsigned)r0 && j < (unsigned)(r0 + RNG)) {
                s_ov[j - r0] = vld[o] ? 2.0f : oldv[o];
                s_id[j - r0] = (unsigned char)o;
            }
        }
        s_any = any;
    }
    __syncthreads();
    if (!s_any) return;   // batch contributes nothing (np stays 0, B skips)

    float ll = 0.f, llm = 0.f, cep = 0.f;
    int np = 0, np1 = 0;
    for (int idx = tid; idx < RNG; idx += 256) {
        const int p = r0 + idx;
        float ov = s_ov[idx];
        int o = s_id[idx];
        int c = (ov < 0.35f) ? 0 : s_lab[o];
        bool pos = (c != 0);

        const float2 cc = *(const float2*)(conf + ((size_t)(b * PN + p)) * 2);
        float c0 = cc.x, c1 = cc.y;

        if (pos) {
            np++;
            float4 q = priors[p];
            float m0 = s_t[o * 4 + 0], m1 = s_t[o * 4 + 1];
            float m2 = s_t[o * 4 + 2], m3 = s_t[o * 4 + 3];
            float isx = 0.1f * q.z, isy = 0.1f * q.w;
            float gx = ((m0 + m2) * 0.5f - q.x) / isx;
            float gy = ((m1 + m3) * 0.5f - q.y) / isy;
            float gw = logf((m2 - m0) / q.z) * 5.0f;
            float gh = logf((m3 - m1) / q.w) * 5.0f;
            const float4 L = *(const float4*)(loc + ((size_t)(b * PN + p)) * 4);
            ll += sl1(L.x - gx) + sl1(L.y - gy) + sl1(L.z - gw) + sl1(L.w - gh);
            if (c > 0) {
                np1++;
                const float* D = landm + ((size_t)(b * PN + p)) * 10;
#pragma unroll
                for (int j = 0; j < 5; j++) {
                    float lx = (s_lm[o * 10 + 2 * j]     - q.x) / isx;
                    float ly = (s_lm[o * 10 + 2 * j + 1] - q.y) / isy;
                    llm += sl1(D[2 * j] - lx) + sl1(D[2 * j + 1] - ly);
                }
            }
        }
        float mx = fmaxf(c0, c1), mn = fminf(c0, c1);
        float lse = mx + __logf(1.f + __expf(mn - mx));
        float ce = lse - (pos ? c1 : c0);
        if (pos) cep += ce;
        g_rank[(size_t)b * PN + p] = pos ? 0.f : ce;
    }

    float wll = warp_sumf(ll), wlm = warp_sumf(llm), wce = warp_sumf(cep);
    int wnp = warp_sumi(np), wnp1 = warp_sumi(np1);
    if (lane == 0) {
        atomicAdd(&r_ll, wll); atomicAdd(&r_lm, wlm); atomicAdd(&r_ce, wce);
        atomicAdd(&r_np, wnp); atomicAdd(&r_np1, wnp1);
    }
    __syncthreads();
    if (tid == 0) {
        if (r_ll != 0.f) atomicAdd(&g_acc[0], r_ll);
        if (r_ce != 0.f) atomicAdd(&g_acc[1], r_ce);
        if (r_lm != 0.f) atomicAdd(&g_acc[2], r_lm);
        if (r_np)  { atomicAdd(&g_cnt[0], r_np); atomicAdd(&g_np[b], r_np); }
        if (r_np1) atomicAdd(&g_cnt[1], r_np1);
    }
}

// =================== loss B: top-k select + sum + finalize ===================
__global__ void __launch_bounds__(1024, 1) k_lossB(float* __restrict__ out)
{
    const int b = blockIdx.x;
    const int tid = threadIdx.x;
    const int lane = tid & 31;

    extern __shared__ float s_r[];
    __shared__ unsigned hist[2048];
    __shared__ unsigned s_pref;
    __shared__ int s_kr;
    __shared__ float s_sum;
    __shared__ int s_cgt;

    const int np = g_np[b];
    const int k = min(7 * np, PN - 1);

    if (k > 0) {
        if (tid == 0) { s_pref = 0; s_kr = k; s_sum = 0.f; s_cgt = 0; }
        for (int i = tid; i < 2048; i += 1024) hist[i] = 0;
        __syncthreads();

        // pass 0: bits[31:21] (11 bits), full scan with aggregated atomics
        for (int i = tid; i < PN; i += 1024) {
            float v = g_rank[(size_t)b * PN + i];
            s_r[i] = v;
            unsigned bin = __float_as_uint(v) >> 21;
            unsigned peers = __match_any_sync(FULLMASK, bin);
            if (lane == __ffs(peers) - 1) atomicAdd(&hist[bin], __popc(peers));
        }
        __syncthreads();
        if (tid == 0) {
            int kr = s_kr;
            unsigned cum = 0; int sel = 0;
            for (int bin = 2047; bin >= 0; bin--) {
                unsigned c = hist[bin];
                if (cum + c >= (unsigned)kr) { sel = bin; break; }
                cum += c;
            }
            s_kr = kr - (int)cum;
            s_pref = (unsigned)sel;
        }
        __syncthreads();

        // pass 1: bits[20:10] among candidates (sparse)
        {
            unsigned pref = s_pref;
            for (int i = tid; i < 2048; i += 1024) hist[i] = 0;
            __syncthreads();
            for (int i = tid; i < PN; i += 1024) {
                unsigned v = __float_as_uint(s_r[i]);
                if ((v >> 21) == pref) atomicAdd(&hist[(v >> 10) & 2047u], 1u);
            }
            __syncthreads();
            if (tid == 0) {
                int kr = s_kr;
                unsigned cum = 0; int sel = 0;
                for (int bin = 2047; bin >= 0; bin--) {
                    unsigned c = hist[bin];
                    if (cum + c >= (unsigned)kr) { sel = bin; break; }
                    cum += c;
                }
                s_kr = kr - (int)cum;
                s_pref = (pref << 11) | (unsigned)sel;
            }
            __syncthreads();
        }

        // pass 2: bits[9:0] among candidates (sparse)
        {
            unsigned pref = s_pref;
            for (int i = tid; i < 1024; i += 1024) hist[i] = 0;
            __syncthreads();
            for (int i = tid; i < PN; i += 1024) {
                unsigned v = __float_as_uint(s_r[i]);
                if ((v >> 10) == pref) atomicAdd(&hist[v & 1023u], 1u);
            }
            __syncthreads();
            if (tid == 0) {
                int kr = s_kr;
                unsigned cum = 0; int sel = 0;
                for (int bin = 1023; bin >= 0; bin--) {
                    unsigned c = hist[bin];
                    if (cum + c >= (unsigned)kr) { sel = bin; break; }
                    cum += c;
                }
                s_kr = kr - (int)cum;
                s_pref = (pref << 10) | (unsigned)sel;
            }
            __syncthreads();
        }

        // final: sum of values strictly above threshold + tie fill
        const float tval = __uint_as_float(s_pref);
        float ls = 0.f; int lc = 0;
        for (int i = tid; i < PN; i += 1024) {
            float v = s_r[i];
            if (v > tval) { ls += v; lc++; }
        }
        ls = warp_sumf(ls); lc = warp_sumi(lc);
        if (lane == 0) { atomicAdd(&s_sum, ls); atomicAdd(&s_cgt, lc); }
        __syncthreads();
        if (tid == 0)
            atomicAdd(&g_acc[1], s_sum + (float)(k - s_cgt) * tval);
    }

    // ---- last-block finalize ----
    __syncthreads();
    if (tid == 0) {
        __threadfence();
        int t = atomicAdd(&g_done, 1);
        if (t == BN - 1) {
            float a0 = *(volatile float*)&g_acc[0];
            float a1 = *(volatile float*)&g_acc[1];
            float a2 = *(volatile float*)&g_acc[2];
            int c0 = *(volatile int*)&g_cnt[0];
            int c1 = *(volatile int*)&g_cnt[1];
            out[0] = a0 / fmaxf((float)c0, 1.f);
            out[1] = a1 / fmaxf((float)c0, 1.f);
            out[2] = a2 / fmaxf((float)c1, 1.f);
            g_done = 0;
        }
    }
}

// =================== launch ===================
extern "C" void kernel_launch(void* const* d_in, const int* in_sizes, int n_in,
                              void* d_out, int out_size) {
    const float* loc = (const float*)d_in[0];
    const float* conf = (const float*)d_in[1];
    const float* landm = (const float*)d_in[2];
    const float4* priors = (const float4*)d_in[3];
    const float* targets = (const float*)d_in[4];
    float* out = (float*)d_out;

    cudaFuncSetAttribute(k_lossB, cudaFuncAttributeMaxDynamicSharedMemorySize, PN * 4);

    dim3 gm(21, BN);
    k_match<<<gm, 256>>>(priors, targets);
    dim3 ga(8, BN);
    k_lossA<<<ga, 256>>>(loc, conf, landm, priors, targets);
    k_lossB<<<BN, 1024, PN * 4>>>(out);
}

// round 6
// speedup vs baseline: 1.1463x; 1.1463x over previous
#include <cuda_runtime.h>

#define PN 16800
#define ON 64
#define BN 64
#define FULLMASK 0xffffffffu

// ---------------- scratch ----------------
__device__ unsigned long long g_bp[BN * ON];
__device__ float g_btov[BN * PN];
__device__ unsigned char g_btidx[BN * PN];
__device__ float g_acc[3];
__device__ int g_cnt[2];
__device__ int g_done;

// =================== matching kernel ===================
// grid (21, 64): bx 0-19 best-truth tiles; bx==20 best-prior per truth + resets
__global__ void __launch_bounds__(256) k_match(
    const float4* __restrict__ priors,
    const float* __restrict__ targets)
{
    const int b = blockIdx.y;
    const int bx = blockIdx.x;
    const int tid = threadIdx.x;
    const int lane = tid & 31;
    const int wid = tid >> 5;

    __shared__ float tX1[ON], tX2[ON], tY1[ON], tY2[ON], tA[ON];

    if (tid < ON) {
        const float* t = targets + (size_t)(b * ON + tid) * 15;
        float x1 = t[0], y1 = t[1], x2 = t[2], y2 = t[3];
        tX1[tid] = x1; tY1[tid] = y1; tX2[tid] = x2; tY2[tid] = y2;
        tA[tid] = (x2 - x1) * (y2 - y1);
    }

    if (bx == 20) {
        // ---------- best prior per truth (grid-separable argmax) ----------
        __shared__ float b_px1[280], b_px2[280], b_py1[280], b_py2[280];
        if (tid < 3) g_acc[tid] = 0.f;
        if (tid >= 3 && tid < 5) g_cnt[tid - 3] = 0;

        for (int t = tid; t < 280; t += 256) {
            int g = (t < 80) ? 0 : (t < 160) ? 1 : (t < 200) ? 2 : (t < 240) ? 3 : (t < 260) ? 4 : 5;
            int off = (g == 0) ? 0 : (g == 1) ? 80 : (g == 2) ? 160 : (g == 3) ? 200 : (g == 4) ? 240 : 260;
            int f = (g < 2) ? 80 : (g < 4) ? 40 : 20;
            int base = (g == 0) ? 0 : (g == 1) ? 6400 : (g == 2) ? 12800 :
                       (g == 3) ? 14400 : (g == 4) ? 16000 : 16400;
            int j = t - off;
            float4 q = priors[base + j];
            b_px1[t] = q.x - q.z * 0.5f; b_px2[t] = q.x + q.z * 0.5f;
            float4 qy = priors[base + j * f];
            b_py1[t] = qy.y - qy.w * 0.5f; b_py2[t] = qy.y + qy.w * 0.5f;
        }
        __syncthreads();

        const int GF[6]   = {80, 80, 40, 40, 20, 20};
        const int GBASE[6]= {0, 6400, 12800, 14400, 16000, 16400};
        const int GOFF[6] = {0, 80, 160, 200, 240, 260};

        for (int it = 0; it < 8; it++) {
            const int o = wid * 8 + it;
            const float X1 = tX1[o], X2 = tX2[o], Y1 = tY1[o], Y2 = tY2[o], A = tA[o];
            unsigned long long best = 0ull;
#pragma unroll
            for (int g = 0; g < 6; g++) {
                const int f = GF[g], co = GOFF[g], base = GBASE[g];
                float bwx = -1.f; int bj = lane;
                for (int j = lane; j < f; j += 32) {
                    float v = fmaxf(fminf(X2, b_px2[co + j]) - fmaxf(X1, b_px1[co + j]), 0.f);
                    if (v > bwx) { bwx = v; bj = j; }
                }
                float bwy = -1.f; int bi2 = lane;
                for (int i = lane; i < f; i += 32) {
                    float v = fmaxf(fminf(Y2, b_py2[co + i]) - fmaxf(Y1, b_py1[co + i]), 0.f);
                    if (v > bwy) { bwy = v; bi2 = i; }
                }
#pragma unroll
                for (int s = 16; s; s >>= 1) {
                    float ov = __shfl_xor_sync(FULLMASK, bwx, s);
                    int oj = __shfl_xor_sync(FULLMASK, bj, s);
                    if (ov > bwx || (ov == bwx && oj < bj)) { bwx = ov; bj = oj; }
                    float ov2 = __shfl_xor_sync(FULLMASK, bwy, s);
                    int oi = __shfl_xor_sync(FULLMASK, bi2, s);
                    if (ov2 > bwy || (ov2 == bwy && oi < bi2)) { bwy = ov2; bi2 = oi; }
                }
                float P = bwx * bwy;
                float dx = b_px2[co + bj] - b_px1[co + bj];
                float dy = b_py2[co + bi2] - b_py1[co + bi2];
                float den = (A + dx * dy) - P;
                float iou = __fdiv_rn(P, den);
                unsigned pidx = (unsigned)(base + bi2 * f + bj);
                unsigned long long key =
                    ((unsigned long long)__float_as_uint(iou) << 32) |
                    (unsigned long long)(0xFFFFFFFFu - pidx);
                if (key > best) best = key;
            }
            if (lane == 0) g_bp[b * ON + o] = best;
        }
        return;
    }

    // ---------- best truth per prior (separable IoU tiles) ----------
    int g, blk;
    if (bx < 7)       { g = 0; blk = bx; }
    else if (bx < 14) { g = 1; blk = bx - 7; }
    else if (bx < 16) { g = 2; blk = bx - 14; }
    else if (bx < 18) { g = 3; blk = bx - 16; }
    else if (bx == 18){ g = 4; blk = 0; }
    else              { g = 5; blk = 0; }
    const int f    = (g < 2) ? 80 : (g < 4) ? 40 : 20;
    const int base = (g == 0) ? 0 : (g == 1) ? 6400 : (g == 2) ? 12800 :
                     (g == 3) ? 14400 : (g == 4) ? 16000 : 16400;
    const int off  = blk * 1024;
    const int n    = min(1024, f * f - off);
    const int i0   = off / f;
    const int nrows = (off + n - 1) / f - i0 + 1;

    __shared__ float s_wx[ON * 80];
    __shared__ float s_wy[ON * 28];
    __shared__ float s_px1[80], s_px2[80], s_dx[80];
    __shared__ float s_py1[28], s_py2[28], s_dy[28];
    __shared__ float cA[ON];
    __shared__ int   cO[ON];
    __shared__ int   s_cnt;

    if (tid >= 64 && tid < 144) {
        int j = tid - 64;
        if (j < f) {
            float4 q = priors[base + j];
            float a = q.x - q.z * 0.5f, c = q.x + q.z * 0.5f;
            s_px1[j] = a; s_px2[j] = c; s_dx[j] = c - a;
        }
    }
    if (tid >= 160 && tid < 192) {
        int r = tid - 160;
        if (r < nrows) {
            float4 q = priors[base + (i0 + r) * f];
            float a = q.y - q.w * 0.5f, c = q.y + q.w * 0.5f;
            s_py1[r] = a; s_py2[r] = c; s_dy[r] = c - a;
        }
    }
    __syncthreads();

    for (int o = wid; o < ON; o += 8) {
        float X1 = tX1[o], X2 = tX2[o];
        for (int j = lane; j < f; j += 32)
            s_wx[o * 80 + j] = fmaxf(fminf(X2, s_px2[j]) - fmaxf(X1, s_px1[j]), 0.f);
        float Y1 = tY1[o], Y2 = tY2[o];
        if (lane < 28)
            s_wy[o * 28 + lane] = (lane < nrows)
                ? fmaxf(fminf(Y2, s_py2[lane]) - fmaxf(Y1, s_py1[lane]), 0.f)
                : 0.f;
    }
    __syncthreads();

    if (tid < 32) {
        float ylo = s_py1[0], yhi = s_py2[nrows - 1];
        unsigned lml = (1u << tid) - 1u;
        int o1 = tid, o2 = tid + 32;
        bool k1 = (tY1[o1] < yhi) && (tY2[o1] > ylo);
        bool k2 = (tY1[o2] < yhi) && (tY2[o2] > ylo);
        unsigned m1 = __ballot_sync(FULLMASK, k1);
        unsigned m2 = __ballot_sync(FULLMASK, k2);
        int n1 = __popc(m1);
        if (k1) { int d = __popc(m1 & lml); cO[d] = o1; cA[d] = tA[o1]; }
        if (k2) { int d = n1 + __popc(m2 & lml); cO[d] = o2; cA[d] = tA[o2]; }
        if (tid == 0) s_cnt = n1 + __popc(m2);
    }
    __syncthreads();

    int jj4[4], rr4[4], pg[4];
    float pa[4], bi[4], bd[4];
    int bo[4];
#pragma unroll
    for (int k = 0; k < 4; k++) {
        bi[k] = 0.f; bd[k] = 1.f; bo[k] = 0;
        int l = tid + k * 256;
        if (l < n) {
            int gi = off + l;
            int i = gi / f;
            int j = gi - i * f;
            rr4[k] = i - i0; jj4[k] = j;
            pa[k] = s_dx[j] * s_dy[i - i0];
            pg[k] = base + gi;
        } else {
            rr4[k] = 27; jj4[k] = 0; pa[k] = 0.f; pg[k] = 0;
        }
    }

    const int cnt = s_cnt;
    for (int c = 0; c < cnt; c++) {
        const int oid = cO[c];
        const float A = cA[c];
        const float* wxo = s_wx + oid * 80;
        const float* wyo = s_wy + oid * 28;
#pragma unroll
        for (int k = 0; k < 4; k++) {
            float inter = wxo[jj4[k]] * wyo[rr4[k]];
            float den = (A + pa[k]) - inter;
            if (inter * bd[k] > bi[k] * den) { bi[k] = inter; bd[k] = den; bo[k] = oid; }
        }
    }

#pragma unroll
    for (int k = 0; k < 4; k++) {
        int l = tid + k * 256;
        if (l < n) {
            g_btov[(size_t)b * PN + pg[k]] = __fdiv_rn(bi[k], bd[k]);
            g_btidx[(size_t)b * PN + pg[k]] = (unsigned char)bo[k];
        }
    }
}

// =================== fused loss kernel: 1 block per batch ===================
__device__ __forceinline__ float sl1(float x) {
    float a = fabsf(x);
    return a < 1.f ? 0.5f * a * a : a - 0.5f;
}
__device__ __forceinline__ float warp_sumf(float v) {
#pragma unroll
    for (int s = 16; s; s >>= 1) v += __shfl_xor_sync(FULLMASK, v, s);
    return v;
}
__device__ __forceinline__ int warp_sumi(int v) {
#pragma unroll
    for (int s = 16; s; s >>= 1) v += __shfl_xor_sync(FULLMASK, v, s);
    return v;
}

#define PADN (17 * 1024)   // PN padded to block-size multiple (collective-safe)

__global__ void __launch_bounds__(1024, 1) k_loss(
    const float* __restrict__ loc,
    const float* __restrict__ conf,
    const float* __restrict__ landm,
    const float4* __restrict__ priors,
    const float* __restrict__ targets,
    float* __restrict__ out)
{
    const int b = blockIdx.x;
    const int tid = threadIdx.x;
    const int lane = tid & 31;

    extern __shared__ float sm[];
    float* s_ov = sm;
    unsigned char* s_id = (unsigned char*)(s_ov + PN);

    __shared__ float s_t[ON * 4];
    __shared__ float s_lm[ON * 10];
    __shared__ int s_lab[ON];
    __shared__ unsigned long long s_keys[ON];
    __shared__ unsigned hist[2048];
    __shared__ float s_ll, s_llm, s_cep, s_sum;
    __shared__ int s_np, s_np1, s_cgt, s_any, s_kr;
    __shared__ unsigned s_pref;

    if (tid == 0) {
        s_ll = 0.f; s_llm = 0.f; s_cep = 0.f; s_sum = 0.f;
        s_np = 0; s_np1 = 0; s_cgt = 0;
    }
    for (int i = tid; i < 2048; i += 1024) hist[i] = 0;
    for (int i = tid; i < PN; i += 1024) {
        s_ov[i] = g_btov[(size_t)b * PN + i];
        s_id[i] = g_btidx[(size_t)b * PN + i];
    }
    if (tid < ON) {
        const float* t = targets + (size_t)(b * ON + tid) * 15;
        s_t[tid * 4 + 0] = t[0]; s_t[tid * 4 + 1] = t[1];
        s_t[tid * 4 + 2] = t[2]; s_t[tid * 4 + 3] = t[3];
#pragma unroll
        for (int j = 0; j < 10; j++) s_lm[tid * 10 + j] = t[4 + j];
        s_lab[tid] = (int)t[14];
        s_keys[tid] = g_bp[b * ON + tid];
    }
    __syncthreads();

    // sequential scatter (last-truth-wins, gathered pre-scatter values)
    if (tid == 0) {
        unsigned js[ON]; int vld[ON]; float oldv[ON];
        int any = 0;
        for (int o = 0; o < ON; o++) {
            unsigned long long key = s_keys[o];
            unsigned j = 0xFFFFFFFFu - (unsigned)(key & 0xFFFFFFFFull);
            js[o] = j;
            vld[o] = (__uint_as_float((unsigned)(key >> 32)) >= 0.2f);
            any |= vld[o];
            oldv[o] = s_ov[j];
        }
        for (int o = 0; o < ON; o++) {
            s_ov[js[o]] = vld[o] ? 2.0f : oldv[o];
            s_id[js[o]] = (unsigned char)o;
        }
        s_any = any;
    }
    __syncthreads();

    if (s_any) {
        // main loop: losses + CE + rank + fused pass-0 histogram (bits[31:21])
        float ll = 0.f, llm = 0.f, cep = 0.f;
        int np = 0, np1 = 0;
        for (int p = tid; p < PADN; p += 1024) {
            const bool in = (p < PN);
            float rank = 0.f;
            if (in) {
                float ov = s_ov[p];
                int o = s_id[p];
                int c = (ov < 0.35f) ? 0 : s_lab[o];
                bool pos = (c != 0);

                const float2 cc = *(const float2*)(conf + ((size_t)(b * PN + p)) * 2);
                float c0 = cc.x, c1 = cc.y;

                if (pos) {
                    np++;
                    float4 q = priors[p];
                    float m0 = s_t[o * 4 + 0], m1 = s_t[o * 4 + 1];
                    float m2 = s_t[o * 4 + 2], m3 = s_t[o * 4 + 3];
                    float isx = 0.1f * q.z, isy = 0.1f * q.w;
                    float gx = ((m0 + m2) * 0.5f - q.x) / isx;
                    float gy = ((m1 + m3) * 0.5f - q.y) / isy;
                    float gw = logf((m2 - m0) / q.z) * 5.0f;
                    float gh = logf((m3 - m1) / q.w) * 5.0f;
                    const float4 L = *(const float4*)(loc + ((size_t)(b * PN + p)) * 4);
                    ll += sl1(L.x - gx) + sl1(L.y - gy) + sl1(L.z - gw) + sl1(L.w - gh);
                    if (c > 0) {
                        np1++;
                        const float* D = landm + ((size_t)(b * PN + p)) * 10;
#pragma unroll
                        for (int j = 0; j < 5; j++) {
                            float lx = (s_lm[o * 10 + 2 * j]     - q.x) / isx;
                            float ly = (s_lm[o * 10 + 2 * j + 1] - q.y) / isy;
                            llm += sl1(D[2 * j] - lx) + sl1(D[2 * j + 1] - ly);
                        }
                    }
                }
                float mx = fmaxf(c0, c1), mn = fminf(c0, c1);
                float lse = mx + __logf(1.f + __expf(mn - mx));
                float ce = lse - (pos ? c1 : c0);
                if (pos) cep += ce;
                rank = pos ? 0.f : ce;
                s_ov[p] = rank;
            }
            // fused 11-bit histogram (all lanes participate; masked by in-range)
            unsigned bin = __float_as_uint(rank) >> 21;
            unsigned okm = __ballot_sync(FULLMASK, in);
            unsigned peers = __match_any_sync(FULLMASK, bin) & okm;
            if (in && lane == (__ffs(peers) - 1)) atomicAdd(&hist[bin], __popc(peers));
        }
        float wll = warp_sumf(ll), wlm = warp_sumf(llm), wce = warp_sumf(cep);
        int wnp = warp_sumi(np), wnp1 = warp_sumi(np1);
        if (lane == 0) {
            atomicAdd(&s_ll, wll); atomicAdd(&s_llm, wlm); atomicAdd(&s_cep, wce);
            atomicAdd(&s_np, wnp); atomicAdd(&s_np1, wnp1);
        }
        __syncthreads();

        const int npos = s_np;
        const int k = min(7 * npos, PN - 1);

        if (k > 0) {
            // select from 11-bit histogram
            if (tid == 0) {
                int kr = k;
                unsigned cum = 0; int sel = 0;
                for (int bin = 2047; bin >= 0; bin--) {
                    unsigned c = hist[bin];
                    if (cum + c >= (unsigned)kr) { sel = bin; break; }
                    cum += c;
                }
                s_kr = kr - (int)cum;
                s_pref = (unsigned)sel;
            }
            __syncthreads();

            // pass 1: bits[20:10] among candidates (sparse, plain atomics)
            {
                unsigned pref = s_pref;
                for (int i = tid; i < 2048; i += 1024) hist[i] = 0;
                __syncthreads();
                for (int i = tid; i < PN; i += 1024) {
                    unsigned v = __float_as_uint(s_ov[i]);
                    if ((v >> 21) == pref) atomicAdd(&hist[(v >> 10) & 2047u], 1u);
                }
                __syncthreads();
                if (tid == 0) {
                    int kr = s_kr;
                    unsigned cum = 0; int sel = 0;
                    for (int bin = 2047; bin >= 0; bin--) {
                        unsigned c = hist[bin];
                        if (cum + c >= (unsigned)kr) { sel = bin; break; }
                        cum += c;
                    }
                    s_kr = kr - (int)cum;
                    s_pref = (pref << 11) | (unsigned)sel;
                }
                __syncthreads();
            }

            // pass 2: bits[9:0] among candidates (sparse, plain atomics)
            {
                unsigned pref = s_pref;
                for (int i = tid; i < 1024; i += 1024) hist[i] = 0;
                __syncthreads();
                for (int i = tid; i < PN; i += 1024) {
                    unsigned v = __float_as_uint(s_ov[i]);
                    if ((v >> 10) == pref) atomicAdd(&hist[v & 1023u], 1u);
                }
                __syncthreads();
                if (tid == 0) {
                    int kr = s_kr;
                    unsigned cum = 0; int sel = 0;
                    for (int bin = 1023; bin >= 0; bin--) {
                        unsigned c = hist[bin];
                        if (cum + c >= (unsigned)kr) { sel = bin; break; }
                        cum += c;
                    }
                    s_kr = kr - (int)cum;
                    s_pref = (pref << 10) | (unsigned)sel;
                }
                __syncthreads();
            }

            // final: sum strictly above threshold + tie fill
            const float tval = __uint_as_float(s_pref);
            float ls = 0.f; int lc = 0;
            for (int i = tid; i < PN; i += 1024) {
                float v = s_ov[i];
                if (v > tval) { ls += v; lc++; }
            }
            ls = warp_sumf(ls); lc = warp_sumi(lc);
            if (lane == 0) { atomicAdd(&s_sum, ls); atomicAdd(&s_cgt, lc); }
            __syncthreads();
        }

        if (tid == 0) {
            float topsum = (k > 0)
                ? (s_sum + (float)(k - s_cgt) * __uint_as_float(s_pref)) : 0.f;
            if (s_ll != 0.f) atomicAdd(&g_acc[0], s_ll);
            float lc = s_cep + topsum;
            if (lc != 0.f) atomicAdd(&g_acc[1], lc);
            if (s_llm != 0.f) atomicAdd(&g_acc[2], s_llm);
            if (s_np)  atomicAdd(&g_cnt[0], s_np);
            if (s_np1) atomicAdd(&g_cnt[1], s_np1);
        }
    }

    // ---- last-block finalize ----
    __syncthreads();
    if (tid == 0) {
        __threadfence();
        int t = atomicAdd(&g_done, 1);
        if (t == BN - 1) {
            float a0 = *(volatile float*)&g_acc[0];
            float a1 = *(volatile float*)&g_acc[1];
            float a2 = *(volatile float*)&g_acc[2];
            int c0 = *(volatile int*)&g_cnt[0];
            int c1 = *(volatile int*)&g_cnt[1];
            out[0] = a0 / fmaxf((float)c0, 1.f);
            out[1] = a1 / fmaxf((float)c0, 1.f);
            out[2] = a2 / fmaxf((float)c1, 1.f);
            g_done = 0;
        }
    }
}

// =================== launch ===================
extern "C" void kernel_launch(void* const* d_in, const int* in_sizes, int n_in,
                              void* d_out, int out_size) {
    const float* loc = (const float*)d_in[0];
    const float* conf = (const float*)d_in[1];
    const float* landm = (const float*)d_in[2];
    const float4* priors = (const float4*)d_in[3];
    const float* targets = (const float*)d_in[4];
    float* out = (float*)d_out;

    const int DYN = PN * 4 + PN;
    cudaFuncSetAttribute(k_loss, cudaFuncAttributeMaxDynamicSharedMemorySize, DYN);

    dim3 gm(21, BN);
    k_match<<<gm, 256>>>(priors, targets);
    k_loss<<<BN, 1024, DYN>>>(loc, conf, landm, priors, targets, out);
}

// round 7
// speedup vs baseline: 2.3588x; 2.0578x over previous
#include <cuda_runtime.h>

#define PN 16800
#define ON 64
#define BN 64
#define FULLMASK 0xffffffffu

// ---------------- scratch ----------------
__device__ unsigned long long g_bp[BN * ON];
__device__ float g_btov[BN * PN];
__device__ unsigned char g_btidx[BN * PN];
__device__ float g_acc[3];
__device__ int g_cnt[2];
__device__ int g_done;

// =================== matching kernel ===================
// grid (21, 64): bx 0-19 best-truth tiles; bx==20 best-prior per truth + resets
__global__ void __launch_bounds__(256) k_match(
    const float4* __restrict__ priors,
    const float* __restrict__ targets)
{
    const int b = blockIdx.y;
    const int bx = blockIdx.x;
    const int tid = threadIdx.x;
    const int lane = tid & 31;
    const int wid = tid >> 5;

    __shared__ float tX1[ON], tX2[ON], tY1[ON], tY2[ON], tA[ON];

    if (tid < ON) {
        const float* t = targets + (size_t)(b * ON + tid) * 15;
        float x1 = t[0], y1 = t[1], x2 = t[2], y2 = t[3];
        tX1[tid] = x1; tY1[tid] = y1; tX2[tid] = x2; tY2[tid] = y2;
        tA[tid] = (x2 - x1) * (y2 - y1);
    }

    if (bx == 20) {
        // ---------- best prior per truth (grid-separable argmax) ----------
        __shared__ float b_px1[280], b_px2[280], b_py1[280], b_py2[280];
        if (tid < 3) g_acc[tid] = 0.f;
        if (tid >= 3 && tid < 5) g_cnt[tid - 3] = 0;

        for (int t = tid; t < 280; t += 256) {
            int g = (t < 80) ? 0 : (t < 160) ? 1 : (t < 200) ? 2 : (t < 240) ? 3 : (t < 260) ? 4 : 5;
            int off = (g == 0) ? 0 : (g == 1) ? 80 : (g == 2) ? 160 : (g == 3) ? 200 : (g == 4) ? 240 : 260;
            int f = (g < 2) ? 80 : (g < 4) ? 40 : 20;
            int base = (g == 0) ? 0 : (g == 1) ? 6400 : (g == 2) ? 12800 :
                       (g == 3) ? 14400 : (g == 4) ? 16000 : 16400;
            int j = t - off;
            float4 q = priors[base + j];
            b_px1[t] = q.x - q.z * 0.5f; b_px2[t] = q.x + q.z * 0.5f;
            float4 qy = priors[base + j * f];
            b_py1[t] = qy.y - qy.w * 0.5f; b_py2[t] = qy.y + qy.w * 0.5f;
        }
        __syncthreads();

        const int GF[6]   = {80, 80, 40, 40, 20, 20};
        const int GBASE[6]= {0, 6400, 12800, 14400, 16000, 16400};
        const int GOFF[6] = {0, 80, 160, 200, 240, 260};

        for (int it = 0; it < 8; it++) {
            const int o = wid * 8 + it;
            const float X1 = tX1[o], X2 = tX2[o], Y1 = tY1[o], Y2 = tY2[o], A = tA[o];
            unsigned long long best = 0ull;
#pragma unroll
            for (int g = 0; g < 6; g++) {
                const int f = GF[g], co = GOFF[g], base = GBASE[g];
                float bwx = -1.f; int bj = lane;
                for (int j = lane; j < f; j += 32) {
                    float v = fmaxf(fminf(X2, b_px2[co + j]) - fmaxf(X1, b_px1[co + j]), 0.f);
                    if (v > bwx) { bwx = v; bj = j; }
                }
                float bwy = -1.f; int bi2 = lane;
                for (int i = lane; i < f; i += 32) {
                    float v = fmaxf(fminf(Y2, b_py2[co + i]) - fmaxf(Y1, b_py1[co + i]), 0.f);
                    if (v > bwy) { bwy = v; bi2 = i; }
                }
#pragma unroll
                for (int s = 16; s; s >>= 1) {
                    float ov = __shfl_xor_sync(FULLMASK, bwx, s);
                    int oj = __shfl_xor_sync(FULLMASK, bj, s);
                    if (ov > bwx || (ov == bwx && oj < bj)) { bwx = ov; bj = oj; }
                    float ov2 = __shfl_xor_sync(FULLMASK, bwy, s);
                    int oi = __shfl_xor_sync(FULLMASK, bi2, s);
                    if (ov2 > bwy || (ov2 == bwy && oi < bi2)) { bwy = ov2; bi2 = oi; }
                }
                float P = bwx * bwy;
                float dx = b_px2[co + bj] - b_px1[co + bj];
                float dy = b_py2[co + bi2] - b_py1[co + bi2];
                float den = (A + dx * dy) - P;
                float iou = __fdiv_rn(P, den);
                unsigned pidx = (unsigned)(base + bi2 * f + bj);
                unsigned long long key =
                    ((unsigned long long)__float_as_uint(iou) << 32) |
                    (unsigned long long)(0xFFFFFFFFu - pidx);
                if (key > best) best = key;
            }
            if (lane == 0) g_bp[b * ON + o] = best;
        }
        return;
    }

    // ---------- best truth per prior (separable IoU tiles) ----------
    int g, blk;
    if (bx < 7)       { g = 0; blk = bx; }
    else if (bx < 14) { g = 1; blk = bx - 7; }
    else if (bx < 16) { g = 2; blk = bx - 14; }
    else if (bx < 18) { g = 3; blk = bx - 16; }
    else if (bx == 18){ g = 4; blk = 0; }
    else              { g = 5; blk = 0; }
    const int f    = (g < 2) ? 80 : (g < 4) ? 40 : 20;
    const int base = (g == 0) ? 0 : (g == 1) ? 6400 : (g == 2) ? 12800 :
                     (g == 3) ? 14400 : (g == 4) ? 16000 : 16400;
    const int off  = blk * 1024;
    const int n    = min(1024, f * f - off);
    const int i0   = off / f;
    const int nrows = (off + n - 1) / f - i0 + 1;

    __shared__ float s_wx[ON * 80];
    __shared__ float s_wy[ON * 28];
    __shared__ float s_px1[80], s_px2[80], s_dx[80];
    __shared__ float s_py1[28], s_py2[28], s_dy[28];
    __shared__ float cA[ON];
    __shared__ int   cO[ON];
    __shared__ int   s_cnt;

    if (tid >= 64 && tid < 144) {
        int j = tid - 64;
        if (j < f) {
            float4 q = priors[base + j];
            float a = q.x - q.z * 0.5f, c = q.x + q.z * 0.5f;
            s_px1[j] = a; s_px2[j] = c; s_dx[j] = c - a;
        }
    }
    if (tid >= 160 && tid < 192) {
        int r = tid - 160;
        if (r < nrows) {
            float4 q = priors[base + (i0 + r) * f];
            float a = q.y - q.w * 0.5f, c = q.y + q.w * 0.5f;
            s_py1[r] = a; s_py2[r] = c; s_dy[r] = c - a;
        }
    }
    __syncthreads();

    for (int o = wid; o < ON; o += 8) {
        float X1 = tX1[o], X2 = tX2[o];
        for (int j = lane; j < f; j += 32)
            s_wx[o * 80 + j] = fmaxf(fminf(X2, s_px2[j]) - fmaxf(X1, s_px1[j]), 0.f);
        float Y1 = tY1[o], Y2 = tY2[o];
        if (lane < 28)
            s_wy[o * 28 + lane] = (lane < nrows)
                ? fmaxf(fminf(Y2, s_py2[lane]) - fmaxf(Y1, s_py1[lane]), 0.f)
                : 0.f;
    }
    __syncthreads();

    if (tid < 32) {
        float ylo = s_py1[0], yhi = s_py2[nrows - 1];
        unsigned lml = (1u << tid) - 1u;
        int o1 = tid, o2 = tid + 32;
        bool k1 = (tY1[o1] < yhi) && (tY2[o1] > ylo);
        bool k2 = (tY1[o2] < yhi) && (tY2[o2] > ylo);
        unsigned m1 = __ballot_sync(FULLMASK, k1);
        unsigned m2 = __ballot_sync(FULLMASK, k2);
        int n1 = __popc(m1);
        if (k1) { int d = __popc(m1 & lml); cO[d] = o1; cA[d] = tA[o1]; }
        if (k2) { int d = n1 + __popc(m2 & lml); cO[d] = o2; cA[d] = tA[o2]; }
        if (tid == 0) s_cnt = n1 + __popc(m2);
    }
    __syncthreads();

    // each thread: 4 CONSECUTIVE priors in one row (n, off, base all mult of 4)
    const int t4 = 4 * tid;
    const bool act = (t4 < n);
    int rr = 27, j0 = 0, pgbase = 0;
    float pa0 = 0.f, pa1 = 0.f, pa2 = 0.f, pa3 = 0.f;
    if (act) {
        int gi = off + t4;
        int i = gi / f;
        j0 = gi - i * f;
        rr = i - i0;
        pgbase = base + gi;
        float dy = s_dy[rr];
        pa0 = s_dx[j0] * dy; pa1 = s_dx[j0 + 1] * dy;
        pa2 = s_dx[j0 + 2] * dy; pa3 = s_dx[j0 + 3] * dy;
    }
    float bi0 = 0.f, bi1 = 0.f, bi2 = 0.f, bi3 = 0.f;
    float bd0 = 1.f, bd1 = 1.f, bd2 = 1.f, bd3 = 1.f;
    int bo0 = 0, bo1 = 0, bo2 = 0, bo3 = 0;

    const int cnt = s_cnt;
    for (int c = 0; c < cnt; c++) {
        const int oid = cO[c];
        const float A = cA[c];
        const float wy = s_wy[oid * 28 + rr];
        const float4 wx4 = *(const float4*)&s_wx[oid * 80 + j0];
        float in0 = wx4.x * wy, in1 = wx4.y * wy;
        float in2 = wx4.z * wy, in3 = wx4.w * wy;
        float de0 = (A + pa0) - in0, de1 = (A + pa1) - in1;
        float de2 = (A + pa2) - in2, de3 = (A + pa3) - in3;
        if (in0 * bd0 > bi0 * de0) { bi0 = in0; bd0 = de0; bo0 = oid; }
        if (in1 * bd1 > bi1 * de1) { bi1 = in1; bd1 = de1; bo1 = oid; }
        if (in2 * bd2 > bi2 * de2) { bi2 = in2; bd2 = de2; bo2 = oid; }
        if (in3 * bd3 > bi3 * de3) { bi3 = in3; bd3 = de3; bo3 = oid; }
    }

    if (act) {
        float4 ov;
        ov.x = __fdiv_rn(bi0, bd0); ov.y = __fdiv_rn(bi1, bd1);
        ov.z = __fdiv_rn(bi2, bd2); ov.w = __fdiv_rn(bi3, bd3);
        *(float4*)&g_btov[(size_t)b * PN + pgbase] = ov;
        uchar4 id4;
        id4.x = (unsigned char)bo0; id4.y = (unsigned char)bo1;
        id4.z = (unsigned char)bo2; id4.w = (unsigned char)bo3;
        *(uchar4*)&g_btidx[(size_t)b * PN + pgbase] = id4;
    }
}

// =================== fused loss kernel: 1 block per batch ===================
__device__ __forceinline__ float sl1(float x) {
    float a = fabsf(x);
    return a < 1.f ? 0.5f * a * a : a - 0.5f;
}
__device__ __forceinline__ float warp_sumf(float v) {
#pragma unroll
    for (int s = 16; s; s >>= 1) v += __shfl_xor_sync(FULLMASK, v, s);
    return v;
}
__device__ __forceinline__ int warp_sumi(int v) {
#pragma unroll
    for (int s = 16; s; s >>= 1) v += __shfl_xor_sync(FULLMASK, v, s);
    return v;
}

#define PADN (17 * 1024)

__global__ void __launch_bounds__(1024, 1) k_loss(
    const float* __restrict__ loc,
    const float* __restrict__ conf,
    const float* __restrict__ landm,
    const float4* __restrict__ priors,
    const float* __restrict__ targets,
    float* __restrict__ out)
{
    const int b = blockIdx.x;
    const int tid = threadIdx.x;
    const int lane = tid & 31;
    const int warp = tid >> 5;

    extern __shared__ float sm[];
    float* s_ov = sm;
    unsigned char* s_id = (unsigned char*)(s_ov + PN);

    __shared__ float s_t[ON * 4];
    __shared__ float s_lm[ON * 10];
    __shared__ int s_lab[ON];
    __shared__ unsigned long long s_keys[ON];
    __shared__ unsigned hist[2048];
    __shared__ unsigned s_wsum[32];
    __shared__ float s_ll, s_llm, s_cep, s_sum;
    __shared__ int s_np, s_np1, s_cgt, s_any, s_kr;
    __shared__ unsigned s_pref;

    if (tid == 0) {
        s_ll = 0.f; s_llm = 0.f; s_cep = 0.f; s_sum = 0.f;
        s_np = 0; s_np1 = 0; s_cgt = 0;
    }
    for (int i = tid; i < PN; i += 1024) {
        s_ov[i] = g_btov[(size_t)b * PN + i];
        s_id[i] = g_btidx[(size_t)b * PN + i];
    }
    if (tid < ON) {
        const float* t = targets + (size_t)(b * ON + tid) * 15;
        s_t[tid * 4 + 0] = t[0]; s_t[tid * 4 + 1] = t[1];
        s_t[tid * 4 + 2] = t[2]; s_t[tid * 4 + 3] = t[3];
#pragma unroll
        for (int j = 0; j < 10; j++) s_lm[tid * 10 + j] = t[4 + j];
        s_lab[tid] = (int)t[14];
        s_keys[tid] = g_bp[b * ON + tid];
    }
    __syncthreads();

    // sequential scatter (last-truth-wins, gathered pre-scatter values)
    if (tid == 0) {
        unsigned js[ON]; int vld[ON]; float oldv[ON];
        int any = 0;
        for (int o = 0; o < ON; o++) {
            unsigned long long key = s_keys[o];
            unsigned j = 0xFFFFFFFFu - (unsigned)(key & 0xFFFFFFFFull);
            js[o] = j;
            vld[o] = (__uint_as_float((unsigned)(key >> 32)) >= 0.2f);
            any |= vld[o];
            oldv[o] = s_ov[j];
        }
        for (int o = 0; o < ON; o++) {
            s_ov[js[o]] = vld[o] ? 2.0f : oldv[o];
            s_id[js[o]] = (unsigned char)o;
        }
        s_any = any;
    }
    __syncthreads();

    if (s_any) {
        // ---- main loop: NO collectives (compiler can pipeline loads) ----
        float ll = 0.f, llm = 0.f, cep = 0.f;
        int np = 0, np1 = 0;
        for (int p = tid; p < PN; p += 1024) {
            float ov = s_ov[p];
            int o = s_id[p];
            int c = (ov < 0.35f) ? 0 : s_lab[o];
            bool pos = (c != 0);

            const float2 cc = *(const float2*)(conf + ((size_t)(b * PN + p)) * 2);
            float c0 = cc.x, c1 = cc.y;

            if (pos) {
                np++;
                float4 q = priors[p];
                float m0 = s_t[o * 4 + 0], m1 = s_t[o * 4 + 1];
                float m2 = s_t[o * 4 + 2], m3 = s_t[o * 4 + 3];
                float isx = 0.1f * q.z, isy = 0.1f * q.w;
                float gx = ((m0 + m2) * 0.5f - q.x) / isx;
                float gy = ((m1 + m3) * 0.5f - q.y) / isy;
                float gw = logf((m2 - m0) / q.z) * 5.0f;
                float gh = logf((m3 - m1) / q.w) * 5.0f;
                const float4 L = *(const float4*)(loc + ((size_t)(b * PN + p)) * 4);
                ll += sl1(L.x - gx) + sl1(L.y - gy) + sl1(L.z - gw) + sl1(L.w - gh);
                if (c > 0) {
                    np1++;
                    const float* D = landm + ((size_t)(b * PN + p)) * 10;
#pragma unroll
                    for (int j = 0; j < 5; j++) {
                        float lx = (s_lm[o * 10 + 2 * j]     - q.x) / isx;
                        float ly = (s_lm[o * 10 + 2 * j + 1] - q.y) / isy;
                        llm += sl1(D[2 * j] - lx) + sl1(D[2 * j + 1] - ly);
                    }
                }
            }
            float mx = fmaxf(c0, c1), mn = fminf(c0, c1);
            float lse = mx + __logf(1.f + __expf(mn - mx));
            float ce = lse - (pos ? c1 : c0);
            if (pos) cep += ce;
            s_ov[p] = pos ? 0.f : ce;
        }
        float wll = warp_sumf(ll), wlm = warp_sumf(llm), wce = warp_sumf(cep);
        int wnp = warp_sumi(np), wnp1 = warp_sumi(np1);
        if (lane == 0) {
            atomicAdd(&s_ll, wll); atomicAdd(&s_llm, wlm); atomicAdd(&s_cep, wce);
            atomicAdd(&s_np, wnp); atomicAdd(&s_np1, wnp1);
        }
        for (int i = tid; i < 2048; i += 1024) hist[i] = 0;
        __syncthreads();

        const int k = min(7 * s_np, PN - 1);
        if (tid == 0) { s_pref = 0; s_kr = k; }

        if (k > 0) {
            // ---- pass 0: 11-bit histogram (padded, collective-safe) ----
            for (int p = tid; p < PADN; p += 1024) {
                bool in = (p < PN);
                unsigned v = in ? __float_as_uint(s_ov[p]) : 0u;
                unsigned bin = v >> 21;
                unsigned okm = __ballot_sync(FULLMASK, in);
                unsigned peers = __match_any_sync(FULLMASK, bin) & okm;
                if (in && (lane == __ffs(peers) - 1))
                    atomicAdd(&hist[bin], (unsigned)__popc(peers));
            }
            __syncthreads();

            // ---- parallel select over 2048 bins ----
            {
                unsigned h0 = hist[2047 - 2 * tid];
                unsigned h1 = hist[2046 - 2 * tid];
                unsigned sv = h0 + h1;
                unsigned inc = sv;
#pragma unroll
                for (int d = 1; d < 32; d <<= 1) {
                    unsigned ot = __shfl_up_sync(FULLMASK, inc, d);
                    if (lane >= d) inc += ot;
                }
                if (lane == 31) s_wsum[warp] = inc;
                __syncthreads();
                if (tid < 32) {
                    unsigned w = s_wsum[tid];
                    unsigned wi = w;
#pragma unroll
                    for (int d = 1; d < 32; d <<= 1) {
                        unsigned ot = __shfl_up_sync(FULLMASK, wi, d);
                        if (tid >= d) wi += ot;
                    }
                    s_wsum[tid] = wi - w;
                }
                __syncthreads();
                unsigned excl = s_wsum[warp] + (inc - sv);
                unsigned kr = (unsigned)s_kr;
                bool x0 = (excl < kr) && (excl + h0 >= kr);
                bool x1 = (excl + h0 < kr) && (excl + h0 + h1 >= kr);
                __syncthreads();
                if (x0) { s_kr = (int)(kr - excl); s_pref = (unsigned)(2047 - 2 * tid); }
                if (x1) { s_kr = (int)(kr - excl - h0); s_pref = (unsigned)(2046 - 2 * tid); }
                __syncthreads();
            }

            // ---- pass 1: bits[20:10], sparse plain atomics ----
            {
                unsigned pref = s_pref;
                for (int i = tid; i < 2048; i += 1024) hist[i] = 0;
                __syncthreads();
                for (int i = tid; i < PN; i += 1024) {
                    unsigned v = __float_as_uint(s_ov[i]);
                    if ((v >> 21) == pref) atomicAdd(&hist[(v >> 10) & 2047u], 1u);
                }
                __syncthreads();
                unsigned h0 = hist[2047 - 2 * tid];
                unsigned h1 = hist[2046 - 2 * tid];
                unsigned sv = h0 + h1;
                unsigned inc = sv;
#pragma unroll
                for (int d = 1; d < 32; d <<= 1) {
                    unsigned ot = __shfl_up_sync(FULLMASK, inc, d);
                    if (lane >= d) inc += ot;
                }
                if (lane == 31) s_wsum[warp] = inc;
                __syncthreads();
                if (tid < 32) {
                    unsigned w = s_wsum[tid];
                    unsigned wi = w;
#pragma unroll
                    for (int d = 1; d < 32; d <<= 1) {
                        unsigned ot = __shfl_up_sync(FULLMASK, wi, d);
                        if (tid >= d) wi += ot;
                    }
                    s_wsum[tid] = wi - w;
                }
                __syncthreads();
                unsigned excl = s_wsum[warp] + (inc - sv);
                unsigned kr = (unsigned)s_kr;
                bool x0 = (excl < kr) && (excl + h0 >= kr);
                bool x1 = (excl + h0 < kr) && (excl + h0 + h1 >= kr);
                __syncthreads();
                if (x0) { s_kr = (int)(kr - excl); s_pref = (pref << 11) | (unsigned)(2047 - 2 * tid); }
                if (x1) { s_kr = (int)(kr - excl - h0); s_pref = (pref << 11) | (unsigned)(2046 - 2 * tid); }
                __syncthreads();
            }

            // ---- pass 2: bits[9:0], sparse plain atomics, 1024 bins ----
            {
                unsigned pref = s_pref;
                for (int i = tid; i < 1024; i += 1024) hist[i] = 0;
                __syncthreads();
                for (int i = tid; i < PN; i += 1024) {
                    unsigned v = __float_as_uint(s_ov[i]);
                    if ((v >> 10) == pref) atomicAdd(&hist[v & 1023u], 1u);
                }
                __syncthreads();
                unsigned h0 = hist[1023 - tid];
                unsigned inc = h0;
#pragma unroll
                for (int d = 1; d < 32; d <<= 1) {
                    unsigned ot = __shfl_up_sync(FULLMASK, inc, d);
                    if (lane >= d) inc += ot;
                }
                if (lane == 31) s_wsum[warp] = inc;
                __syncthreads();
                if (tid < 32) {
                    unsigned w = s_wsum[tid];
                    unsigned wi = w;
#pragma unroll
                    for (int d = 1; d < 32; d <<= 1) {
                        unsigned ot = __shfl_up_sync(FULLMASK, wi, d);
                        if (tid >= d) wi += ot;
                    }
                    s_wsum[tid] = wi - w;
                }
                __syncthreads();
                unsigned excl = s_wsum[warp] + (inc - h0);
                unsigned kr = (unsigned)s_kr;
                bool x0 = (excl < kr) && (excl + h0 >= kr);
                __syncthreads();
                if (x0) { s_kr = (int)(kr - excl); s_pref = (pref << 10) | (unsigned)(1023 - tid); }
                __syncthreads();
            }

            // ---- final: sum strictly above threshold + tie fill ----
            const float tval = __uint_as_float(s_pref);
            float ls = 0.f; int lc = 0;
            for (int i = tid; i < PN; i += 1024) {
                float v = s_ov[i];
                if (v > tval) { ls += v; lc++; }
            }
            ls = warp_sumf(ls); lc = warp_sumi(lc);
            if (lane == 0) { atomicAdd(&s_sum, ls); atomicAdd(&s_cgt, lc); }
            __syncthreads();
        } else {
            __syncthreads();
        }

        if (tid == 0) {
            float topsum = (k > 0)
                ? (s_sum + (float)(k - s_cgt) * __uint_as_float(s_pref)) : 0.f;
            if (s_ll != 0.f) atomicAdd(&g_acc[0], s_ll);
            float lc = s_cep + topsum;
            if (lc != 0.f) atomicAdd(&g_acc[1], lc);
            if (s_llm != 0.f) atomicAdd(&g_acc[2], s_llm);
            if (s_np)  atomicAdd(&g_cnt[0], s_np);
            if (s_np1) atomicAdd(&g_cnt[1], s_np1);
        }
    }

    // ---- last-block finalize ----
    __syncthreads();
    if (tid == 0) {
        __threadfence();
        int t = atomicAdd(&g_done, 1);
        if (t == BN - 1) {
            float a0 = *(volatile float*)&g_acc[0];
            float a1 = *(volatile float*)&g_acc[1];
            float a2 = *(volatile float*)&g_acc[2];
            int c0 = *(volatile int*)&g_cnt[0];
            int c1 = *(volatile int*)&g_cnt[1];
            out[0] = a0 / fmaxf((float)c0, 1.f);
            out[1] = a1 / fmaxf((float)c0, 1.f);
            out[2] = a2 / fmaxf((float)c1, 1.f);
            g_done = 0;
        }
    }
}

// =================== launch ===================
extern "C" void kernel_launch(void* const* d_in, const int* in_sizes, int n_in,
                              void* d_out, int out_size) {
    const float* loc = (const float*)d_in[0];
    const float* conf = (const float*)d_in[1];
    const float* landm = (const float*)d_in[2];
    const float4* priors = (const float4*)d_in[3];
    const float* targets = (const float*)d_in[4];
    float* out = (float*)d_out;

    const int DYN = PN * 4 + PN;
    cudaFuncSetAttribute(k_loss, cudaFuncAttributeMaxDynamicSharedMemorySize, DYN);

    dim3 gm(21, BN);
    k_match<<<gm, 256>>>(priors, targets);
    k_loss<<<BN, 1024, DYN>>>(loc, conf, landm, priors, targets, out);
}